// round 4
// baseline (speedup 1.0000x reference)
#include <cuda_runtime.h>
#include <cstdint>

#define BB 2
#define DD 512
#define KK 32
#define NN 4096
#define NB 64          // n per tile (assign)
#define DC 64          // d chunk (assign)
#define NCH 8          // n chunks (aggregate)
#define ZSIZE (BB*DD*KK)
#define GRID 128
#define NTHR 256

// ---------- device scratch ----------
__device__ float g_C[KK];                    // sum_d s^2 c^2
__device__ float g_S1part[GRID*KK];          // per-tile Q column sums
__device__ float g_Mpart[NCH][BB*DD*KK];     // partial M = sum_n Q*x
__device__ float g_SS[BB*64*KK];             // per-dtile sumsq partials
__device__ volatile unsigned g_bar;          // grid barrier counter

// ---------- f32x2 helpers ----------
__device__ __forceinline__ unsigned long long pk2(float lo, float hi) {
    unsigned long long r;
    asm("mov.b64 %0, {%1,%2};" : "=l"(r) : "f"(lo), "f"(hi));
    return r;
}
__device__ __forceinline__ void upk2(unsigned long long v, float& lo, float& hi) {
    asm("mov.b64 {%0,%1}, %2;" : "=f"(lo), "=f"(hi) : "l"(v));
}
__device__ __forceinline__ unsigned long long fma2(unsigned long long a,
                                                   unsigned long long b,
                                                   unsigned long long c) {
    unsigned long long d;
    asm("fma.rn.f32x2 %0, %1, %2, %3;" : "=l"(d) : "l"(a), "l"(b), "l"(c));
    return d;
}

// ---------- grid barrier (all 128 blocks co-resident; counter reset by reset_kernel) ----------
__device__ __forceinline__ void grid_sync(unsigned target) {
    __syncthreads();
    if (threadIdx.x == 0) {
        __threadfence();
        atomicAdd((unsigned*)&g_bar, 1u);
        while (g_bar < target) { __nanosleep(32); }
        __threadfence();
    }
    __syncthreads();
}

__global__ void reset_kernel() {
    if (threadIdx.x == 0) g_bar = 0;
}

// ---------- smem layout (dynamic, 74784 B) ----------
#define OFF_XS 0        // float  [DC][NB]    16384
#define OFF_AS 16384    // ull    [DC][KK]    16384
#define OFF_BS 32768    // ull    [DC][KK]    16384
#define OFF_CW 49152    // float  [KK][65]     8320
#define OFF_EP 0        // float  [8][NB][KK] 65536 (alias, post-compute)
#define OFF_EF 65536    // float  [NB][KK]     8192
#define OFF_S1 73728    // float  [8][33]      1056
#define SMEM_TOTAL 74784

__global__ __launch_bounds__(NTHR) void fused_kernel(const float* __restrict__ X,
                                                     const float* __restrict__ cw,
                                                     const float* __restrict__ scale,
                                                     float* __restrict__ out) {
    extern __shared__ unsigned char sm[];
    const int tid  = threadIdx.x;
    const int lane = tid & 31;
    const int w    = tid >> 5;
    const int bid  = blockIdx.x;

    // ============ P0: C[k] = sum_d s^2 c^2 (blocks 0..31) ============
    if (bid < KK) {
        float* red = (float*)sm;   // 256 floats
        const int k = bid;
        float csum = 0.f;
        #pragma unroll
        for (int i = 0; i < 2; i++) {
            int d = tid + i*256;
            float s = scale[d*KK + k];
            float c = cw[k*DD + d];
            csum += s*s*c*c;
        }
        red[tid] = csum; __syncthreads();
        #pragma unroll
        for (int off = 128; off > 0; off >>= 1) {
            if (tid < off) red[tid] += red[tid + off];
            __syncthreads();
        }
        if (tid == 0) g_C[k] = red[0];
    }
    grid_sync(1*GRID);

    // ============ P1: assign — E-GEMM + softmax -> Q ============
    {
        float*              Xs   = (float*)(sm + OFF_XS);
        unsigned long long* As   = (unsigned long long*)(sm + OFF_AS);
        unsigned long long* Bs   = (unsigned long long*)(sm + OFF_BS);
        float*              cwsh = (float*)(sm + OFF_CW);

        const int n0 = bid * NB;
        const int b  = n0 >> 12;
        const float* Xb = X + (size_t)b * DD * NN + (n0 & (NN - 1));

        unsigned long long acc[NB/2];
        #pragma unroll
        for (int i = 0; i < NB/2; i++) acc[i] = 0ull;

        for (int dc = 0; dc < DD; dc += DC) {
            // stage X tile [DC][NB]
            #pragma unroll
            for (int it = 0; it < 4; it++) {
                int idx = tid + it*256;
                int r = idx >> 4, c4 = idx & 15;
                *(float4*)&Xs[r*NB + c4*4] =
                    *(const float4*)(Xb + (size_t)(dc + r)*NN + c4*4);
            }
            // stage cw chunk transposed: cwsh[k][d_local]
            #pragma unroll
            for (int it = 0; it < 8; it++) {
                int idx = tid + it*256;
                int k = idx >> 6, d = idx & 63;
                cwsh[k*65 + d] = cw[k*DD + dc + d];
            }
            __syncthreads();
            // compute packed coefficients a = s^2, b = -2 s^2 c
            #pragma unroll
            for (int it = 0; it < 8; it++) {
                int idx = tid + it*256;
                int d = idx >> 5, k = idx & 31;
                float s  = scale[(dc + d)*KK + k];
                float c  = cwsh[k*65 + d];
                float s2 = s*s;
                float bc = -2.f*s2*c;
                As[d*KK + k] = pk2(s2, s2);
                Bs[d*KK + k] = pk2(bc, bc);
            }
            __syncthreads();
            // warp w handles d = dc+w, dc+w+8, ...
            for (int dd = w; dd < DC; dd += 8) {
                unsigned long long a2 = As[dd*KK + lane];
                unsigned long long b2 = Bs[dd*KK + lane];
                const float* xr = &Xs[dd*NB];
                #pragma unroll
                for (int g = 0; g < NB/4; g++) {
                    longlong2 xv = *reinterpret_cast<const longlong2*>(xr + g*4);
                    unsigned long long x01 = (unsigned long long)xv.x;
                    unsigned long long x23 = (unsigned long long)xv.y;
                    unsigned long long t0 = fma2(a2, x01, b2);
                    acc[2*g]   = fma2(x01, t0, acc[2*g]);
                    unsigned long long t1 = fma2(a2, x23, b2);
                    acc[2*g+1] = fma2(x23, t1, acc[2*g+1]);
                }
            }
            __syncthreads();
        }

        // per-warp partial dump (aliases staging buffers)
        float* Ep = (float*)(sm + OFF_EP);
        float* Ef = (float*)(sm + OFF_EF);
        float* s1red = (float*)(sm + OFF_S1);
        #pragma unroll
        for (int i = 0; i < NB/2; i++) {
            float lo, hi; upk2(acc[i], lo, hi);
            Ep[(w*NB + 2*i  )*KK + lane] = lo;
            Ep[(w*NB + 2*i+1)*KK + lane] = hi;
        }
        __syncthreads();
        for (int idx = tid; idx < NB*KK; idx += 256) {
            float s = Ep[idx];
            #pragma unroll
            for (int ww = 1; ww < 8; ww++) s += Ep[ww*NB*KK + idx];
            Ef[idx] = s;
        }
        __syncthreads();

        // softmax over k (lanes); warp w handles 8 n
        float* Qout = out + ZSIZE;
        const float Ck = g_C[lane];
        float s1loc = 0.f;
        #pragma unroll
        for (int i = 0; i < 8; i++) {
            int n = w*8 + i;
            float arg = -0.5f * (Ef[n*KK + lane] + Ck);
            float m = arg;
            #pragma unroll
            for (int off = 16; off; off >>= 1) m = fmaxf(m, __shfl_xor_sync(~0u, m, off));
            float ex = __expf(arg - m);
            float ssum = ex;
            #pragma unroll
            for (int off = 16; off; off >>= 1) ssum += __shfl_xor_sync(~0u, ssum, off);
            float q = ex / ssum;
            Qout[(size_t)(n0 + n)*KK + lane] = q;
            s1loc += q;
        }
        s1red[w*33 + lane] = s1loc;
        __syncthreads();
        if (w == 0) {
            float s = 0.f;
            #pragma unroll
            for (int i = 0; i < 8; i++) s += s1red[i*33 + lane];
            g_S1part[bid*KK + lane] = s;
        }
    }
    grid_sync(2*GRID);

    // ============ P2: aggregate Mpart[nc][b,d,k] = sum_n Q*x ============
    {
        float* Xs2 = (float*)(sm + 0);       // [64][64] 16KB
        float* Qs  = (float*)(sm + 16384);   // [64][32] 8KB
        const int b  = bid >> 6;
        const int dt = (bid >> 3) & 7;
        const int nc = bid & 7;
        const int d0 = dt*64;
        const int nb0 = nc*(NN/NCH);

        const float* Qb = out + ZSIZE + (size_t)b*NN*KK;
        const float* Xb = X + (size_t)b*DD*NN;

        unsigned long long acc2[8];
        #pragma unroll
        for (int j = 0; j < 8; j++) acc2[j] = 0ull;

        #pragma unroll 1
        for (int s = 0; s < (NN/NCH)/64; s++) {   // 8 subtiles of 64 n
            int nbase = nb0 + s*64;
            #pragma unroll
            for (int it = 0; it < 4; it++) {
                int i2 = tid + it*256; int r = i2 >> 4, c4 = i2 & 15;
                *(float4*)&Xs2[r*64 + c4*4] =
                    *(const float4*)(Xb + (size_t)(d0 + r)*NN + nbase + c4*4);
            }
            #pragma unroll
            for (int it = 0; it < 2; it++) {
                int i2 = tid + it*256;
                *(float4*)&Qs[i2*4] = *(const float4*)(Qb + (size_t)nbase*KK + i2*4);
            }
            __syncthreads();
            #pragma unroll
            for (int g = 0; g < 16; g++) {
                float q0 = Qs[(4*g+0)*KK + lane];
                float q1 = Qs[(4*g+1)*KK + lane];
                float q2 = Qs[(4*g+2)*KK + lane];
                float q3 = Qs[(4*g+3)*KK + lane];
                unsigned long long q01 = pk2(q0, q1), q23 = pk2(q2, q3);
                #pragma unroll
                for (int j = 0; j < 8; j++) {
                    longlong2 xv = *reinterpret_cast<const longlong2*>(&Xs2[(w*8+j)*64 + 4*g]);
                    acc2[j] = fma2(q01, (unsigned long long)xv.x, acc2[j]);
                    acc2[j] = fma2(q23, (unsigned long long)xv.y, acc2[j]);
                }
            }
            __syncthreads();
        }
        #pragma unroll
        for (int j = 0; j < 8; j++) {
            float lo, hi; upk2(acc2[j], lo, hi);
            g_Mpart[nc][((size_t)b*DD + d0 + w*8 + j)*KK + lane] = lo + hi;
        }
    }
    grid_sync(3*GRID);

    // ============ P3: unnormalized Z + sumsq partials ============
    const int bf  = bid >> 6;
    const int dtf = bid & 63;
    const int d0f = dtf*8;
    const int df  = d0f + w;            // warp w owns one d, lane = k
    const size_t mi = ((size_t)bf*DD + df)*KK + lane;
    {
        float* red  = (float*)(sm + 0);     // [8][33]
        float* cwf  = (float*)(sm + 2048);  // [32][9]
        float* bsh  = (float*)(sm + 3328);  // [32]

        // stage cw[k][d0f..d0f+7]
        {
            int k = tid >> 3, dl = tid & 7;
            cwf[k*9 + dl] = cw[k*DD + d0f + dl];
        }
        // S1[b,k] (fixed-order partial + tree)
        float s1p = 0.f;
        #pragma unroll
        for (int j = 0; j < 8; j++)
            s1p += g_S1part[(bf*64 + w + 8*j)*KK + lane];
        red[w*33 + lane] = s1p;
        __syncthreads();
        if (w == 0) {
            float s = 0.f;
            #pragma unroll
            for (int i = 0; i < 8; i++) s += red[i*33 + lane];
            bsh[lane] = 1.f / s;
        }
        __syncthreads();
        const float inv_s1 = bsh[lane];

        float m = 0.f;
        #pragma unroll
        for (int c = 0; c < NCH; c++) m += g_Mpart[c][mi];
        float z = scale[df*KK + lane] * (m*inv_s1 - cwf[lane*9 + w]);
        out[mi] = z;
        __syncthreads();
        red[w*33 + lane] = z*z;
        __syncthreads();
        if (w == 0) {
            float s = 0.f;
            #pragma unroll
            for (int i = 0; i < 8; i++) s += red[i*33 + lane];
            g_SS[(bf*64 + dtf)*KK + lane] = s;
        }
    }
    grid_sync(4*GRID);

    // ============ P4: rescale by 1/sqrt(sum_d z^2) ============
    {
        float* red = (float*)(sm + 0);
        float* bsh = (float*)(sm + 3328);
        float ssp = 0.f;
        #pragma unroll
        for (int j = 0; j < 8; j++)
            ssp += g_SS[(bf*64 + w + 8*j)*KK + lane];
        red[w*33 + lane] = ssp;
        __syncthreads();
        if (w == 0) {
            float s = 0.f;
            #pragma unroll
            for (int i = 0; i < 8; i++) s += red[i*33 + lane];
            bsh[lane] = rsqrtf(s);
        }
        __syncthreads();
        out[mi] *= bsh[lane];
    }
}

extern "C" void kernel_launch(void* const* d_in, const int* in_sizes, int n_in,
                              void* d_out, int out_size) {
    const float* X     = (const float*)d_in[0];
    const float* cw    = (const float*)d_in[1];
    const float* scale = (const float*)d_in[2];
    float* out = (float*)d_out;

    static int configured = 0;
    if (!configured) {
        cudaFuncSetAttribute(fused_kernel, cudaFuncAttributeMaxDynamicSharedMemorySize,
                             SMEM_TOTAL);
        configured = 1;
    }

    reset_kernel<<<1, 32>>>();
    fused_kernel<<<GRID, NTHR, SMEM_TOTAL>>>(X, cw, scale, out);
}

// round 5
// speedup vs baseline: 1.0842x; 1.0842x over previous
#include <cuda_runtime.h>
#include <cstdint>

#define BB 2
#define DD 512
#define KK 32
#define NN 4096
#define NB 64          // n per tile (assign)
#define DC 64          // d chunk (assign)
#define NCH 8          // n chunks (aggregate)
#define ZSIZE (BB*DD*KK)
#define GRID 128
#define NTHR 512

// ---------- device scratch ----------
__device__ unsigned long long g_A2[DD*KK];   // (s^2,s^2) packed
__device__ unsigned long long g_B2[DD*KK];   // (-2 s^2 c) packed
__device__ float g_C[KK];                    // sum_d s^2 c^2
__device__ float g_S1part[GRID*KK];          // per-tile Q column sums
__device__ float g_Mpart[NCH][BB*DD*KK];     // partial M = sum_n Q*x
__device__ float g_SS[BB*64*KK];             // per-dtile sumsq partials
__device__ volatile unsigned g_bar;          // grid barrier counter

// ---------- f32x2 helpers ----------
__device__ __forceinline__ unsigned long long pk2(float lo, float hi) {
    unsigned long long r;
    asm("mov.b64 %0, {%1,%2};" : "=l"(r) : "f"(lo), "f"(hi));
    return r;
}
__device__ __forceinline__ void upk2(unsigned long long v, float& lo, float& hi) {
    asm("mov.b64 {%0,%1}, %2;" : "=f"(lo), "=f"(hi) : "l"(v));
}
__device__ __forceinline__ unsigned long long fma2(unsigned long long a,
                                                   unsigned long long b,
                                                   unsigned long long c) {
    unsigned long long d;
    asm("fma.rn.f32x2 %0, %1, %2, %3;" : "=l"(d) : "l"(a), "l"(b), "l"(c));
    return d;
}

// ---------- grid barrier ----------
__device__ __forceinline__ void grid_sync(unsigned target) {
    __syncthreads();
    if (threadIdx.x == 0) {
        __threadfence();
        atomicAdd((unsigned*)&g_bar, 1u);
        while (g_bar < target) { __nanosleep(32); }
        __threadfence();
    }
    __syncthreads();
}

__global__ void reset_kernel() {
    if (threadIdx.x == 0) g_bar = 0;
}

// ---------- smem layout ----------
// staging phase: Xs [64][64] 16K @0 ; As 16K @16384 ; Bs 16K @32768
// epilogue alias: Ep [16][32][32] 64K @0 ; Ef [64][32] 8K @65536 ; red [16][33] @73728
#define OFF_AS 16384
#define OFF_BS 32768
#define OFF_EF 65536
#define OFF_RED 73728
#define SMEM_TOTAL (73728 + 16*33*4)

__global__ __launch_bounds__(NTHR) void fused_kernel(const float* __restrict__ X,
                                                     const float* __restrict__ cw,
                                                     const float* __restrict__ scale,
                                                     float* __restrict__ out) {
    extern __shared__ unsigned char sm[];
    const int tid  = threadIdx.x;
    const int lane = tid & 31;
    const int w    = tid >> 5;           // 0..15
    const int bid  = blockIdx.x;

    // ============ P0: coefficients ============
    // all blocks: 128 (d,k) entries each for A2/B2; blocks 0..31: C[k]
    if (tid < 128) {
        int idx = bid*128 + tid;         // 0..16383 = d*32+k
        float s  = scale[idx];
        int d = idx >> 5, k = idx & 31;
        float c  = cw[k*DD + d];
        float s2 = s*s;
        float bc = -2.f*s2*c;
        g_A2[idx] = pk2(s2, s2);
        g_B2[idx] = pk2(bc, bc);
    }
    if (bid < KK) {
        float* red = (float*)sm;         // 512 floats
        const int k = bid;
        float s = scale[tid*KK + k];
        float c = cw[k*DD + tid];
        red[tid] = s*s*c*c;
        __syncthreads();
        #pragma unroll
        for (int off = 256; off > 0; off >>= 1) {
            if (tid < off) red[tid] += red[tid + off];
            __syncthreads();
        }
        if (tid == 0) g_C[k] = red[0];
    }
    grid_sync(1*GRID);

    // ============ P1: assign — E-GEMM + softmax -> Q ============
    {
        float*              Xs = (float*)(sm);
        unsigned long long* As = (unsigned long long*)(sm + OFF_AS);
        unsigned long long* Bs = (unsigned long long*)(sm + OFF_BS);

        const int ng = w >> 3;           // n group 0/1 (32 n each)
        const int wd = w & 7;            // d-row subset within group
        const int n0 = bid * NB;
        const int b  = n0 >> 12;
        const float* Xb = X + (size_t)b * DD * NN + (n0 & (NN - 1));

        unsigned long long acc[16];
        #pragma unroll
        for (int i = 0; i < 16; i++) acc[i] = 0ull;

        for (int dc = 0; dc < DD; dc += DC) {
            // stage X tile [64][64] : 1024 float4
            #pragma unroll
            for (int it = 0; it < 2; it++) {
                int idx = tid + it*512;
                int r = idx >> 4, c4 = idx & 15;
                *(float4*)&Xs[r*NB + c4*4] =
                    *(const float4*)(Xb + (size_t)(dc + r)*NN + c4*4);
            }
            // stage coefficients: 1024 float4 each
            const float4* gA4 = (const float4*)(g_A2 + dc*KK);
            const float4* gB4 = (const float4*)(g_B2 + dc*KK);
            #pragma unroll
            for (int it = 0; it < 2; it++) {
                int idx = tid + it*512;
                ((float4*)As)[idx] = gA4[idx];
                ((float4*)Bs)[idx] = gB4[idx];
            }
            __syncthreads();
            // warp (ng,wd): d rows wd, wd+8, ... ; n columns [ng*32, ng*32+32)
            for (int dd = wd; dd < DC; dd += 8) {
                unsigned long long a2 = As[dd*KK + lane];
                unsigned long long b2 = Bs[dd*KK + lane];
                const float* xr = &Xs[dd*NB + ng*32];
                #pragma unroll
                for (int g = 0; g < 8; g++) {
                    longlong2 xv = *reinterpret_cast<const longlong2*>(xr + g*4);
                    unsigned long long x01 = (unsigned long long)xv.x;
                    unsigned long long x23 = (unsigned long long)xv.y;
                    unsigned long long t0 = fma2(a2, x01, b2);
                    acc[2*g]   = fma2(x01, t0, acc[2*g]);
                    unsigned long long t1 = fma2(a2, x23, b2);
                    acc[2*g+1] = fma2(x23, t1, acc[2*g+1]);
                }
            }
            __syncthreads();
        }

        // dump per-warp partials: Ep[w][nl(32)][k(32)]
        float* Ep  = (float*)sm;
        float* Ef  = (float*)(sm + OFF_EF);
        float* red = (float*)(sm + OFF_RED);
        #pragma unroll
        for (int i = 0; i < 16; i++) {
            float lo, hi; upk2(acc[i], lo, hi);
            Ep[w*1024 + (2*i  )*KK + lane] = lo;
            Ep[w*1024 + (2*i+1)*KK + lane] = hi;
        }
        __syncthreads();
        // reduce 8 warps within each n-group: Ef[idx], idx = ng*1024 + nl*32 + k
        #pragma unroll
        for (int it = 0; it < 4; it++) {
            int idx = tid + it*512;
            int g2  = idx >> 10;         // n group
            int rem = idx & 1023;
            float s = 0.f;
            #pragma unroll
            for (int ww = 0; ww < 8; ww++) s += Ep[(g2*8 + ww)*1024 + rem];
            Ef[idx] = s;
        }
        __syncthreads();

        // softmax: warp w handles n = w*4 + i
        float* Qout = out + ZSIZE;
        const float Ck = g_C[lane];
        float s1loc = 0.f;
        #pragma unroll
        for (int i = 0; i < 4; i++) {
            int n = w*4 + i;
            float arg = -0.5f * (Ef[n*KK + lane] + Ck);
            float m = arg;
            #pragma unroll
            for (int off = 16; off; off >>= 1) m = fmaxf(m, __shfl_xor_sync(~0u, m, off));
            float ex = __expf(arg - m);
            float ssum = ex;
            #pragma unroll
            for (int off = 16; off; off >>= 1) ssum += __shfl_xor_sync(~0u, ssum, off);
            float q = ex / ssum;
            Qout[(size_t)(n0 + n)*KK + lane] = q;
            s1loc += q;
        }
        red[w*33 + lane] = s1loc;
        __syncthreads();
        if (w == 0) {
            float s = 0.f;
            #pragma unroll
            for (int i = 0; i < 16; i++) s += red[i*33 + lane];
            g_S1part[bid*KK + lane] = s;
        }
    }
    grid_sync(2*GRID);

    // ============ P2: aggregate Mpart[nc][b,d,k] = sum_n Q*x ============
    {
        float* Xs2 = (float*)(sm);           // [64][64] 16KB
        float* Qs  = (float*)(sm + 16384);   // [64][32] 8KB
        const int b  = bid >> 6;
        const int dt = (bid >> 3) & 7;
        const int nc = bid & 7;
        const int d0 = dt*64;
        const int nb0 = nc*(NN/NCH);

        const float* Qb = out + ZSIZE + (size_t)b*NN*KK;
        const float* Xb = X + (size_t)b*DD*NN;

        unsigned long long acc2[4];
        #pragma unroll
        for (int j = 0; j < 4; j++) acc2[j] = 0ull;

        #pragma unroll 1
        for (int s = 0; s < (NN/NCH)/64; s++) {   // 8 subtiles of 64 n
            int nbase = nb0 + s*64;
            #pragma unroll
            for (int it = 0; it < 2; it++) {
                int i2 = tid + it*512; int r = i2 >> 4, c4 = i2 & 15;
                *(float4*)&Xs2[r*64 + c4*4] =
                    *(const float4*)(Xb + (size_t)(d0 + r)*NN + nbase + c4*4);
            }
            *(float4*)&Qs[tid*4] = *(const float4*)(Qb + (size_t)nbase*KK + tid*4);
            __syncthreads();
            #pragma unroll
            for (int g = 0; g < 16; g++) {
                float q0 = Qs[(4*g+0)*KK + lane];
                float q1 = Qs[(4*g+1)*KK + lane];
                float q2 = Qs[(4*g+2)*KK + lane];
                float q3 = Qs[(4*g+3)*KK + lane];
                unsigned long long q01 = pk2(q0, q1), q23 = pk2(q2, q3);
                #pragma unroll
                for (int j = 0; j < 4; j++) {
                    longlong2 xv = *reinterpret_cast<const longlong2*>(&Xs2[(w*4+j)*64 + 4*g]);
                    acc2[j] = fma2(q01, (unsigned long long)xv.x, acc2[j]);
                    acc2[j] = fma2(q23, (unsigned long long)xv.y, acc2[j]);
                }
            }
            __syncthreads();
        }
        #pragma unroll
        for (int j = 0; j < 4; j++) {
            float lo, hi; upk2(acc2[j], lo, hi);
            g_Mpart[nc][((size_t)b*DD + d0 + w*4 + j)*KK + lane] = lo + hi;
        }
    }
    grid_sync(3*GRID);

    // ============ P3: unnormalized Z + sumsq partials ============
    const int bf  = bid >> 6;
    const int dtf = bid & 63;
    const int d0f = dtf*8;
    const int df  = d0f + (w & 7);
    const size_t mi = ((size_t)bf*DD + df)*KK + lane;
    {
        float* red = (float*)(sm);          // [16][33]
        float* cwf = (float*)(sm + 4096);   // [32][9]
        float* bsh = (float*)(sm + 6144);   // [32]

        if (tid < 256) {
            int k = tid >> 3, dl = tid & 7;
            cwf[k*9 + dl] = cw[k*DD + d0f + dl];
        }
        // S1[b,k]: 64 partials, each warp sums 4 fixed-order
        float s1p = 0.f;
        #pragma unroll
        for (int j = 0; j < 4; j++)
            s1p += g_S1part[(bf*64 + w + 16*j)*KK + lane];
        red[w*33 + lane] = s1p;
        __syncthreads();
        if (w == 0) {
            float s = 0.f;
            #pragma unroll
            for (int i = 0; i < 16; i++) s += red[i*33 + lane];
            bsh[lane] = 1.f / s;
        }
        __syncthreads();

        float z = 0.f;
        if (w < 8) {
            const float inv_s1 = bsh[lane];
            float m = 0.f;
            #pragma unroll
            for (int c = 0; c < NCH; c++) m += g_Mpart[c][mi];
            z = scale[df*KK + lane] * (m*inv_s1 - cwf[lane*9 + (w & 7)]);
            out[mi] = z;
        }
        __syncthreads();
        if (w < 8) red[w*33 + lane] = z*z;
        __syncthreads();
        if (w == 0) {
            float s = 0.f;
            #pragma unroll
            for (int i = 0; i < 8; i++) s += red[i*33 + lane];
            g_SS[(bf*64 + dtf)*KK + lane] = s;
        }
    }
    grid_sync(4*GRID);

    // ============ P4: rescale by 1/sqrt(sum_d z^2) ============
    {
        float* red = (float*)(sm);
        float* bsh = (float*)(sm + 6144);
        float ssp = 0.f;
        #pragma unroll
        for (int j = 0; j < 4; j++)
            ssp += g_SS[(bf*64 + w + 16*j)*KK + lane];
        red[w*33 + lane] = ssp;
        __syncthreads();
        if (w == 0) {
            float s = 0.f;
            #pragma unroll
            for (int i = 0; i < 16; i++) s += red[i*33 + lane];
            bsh[lane] = rsqrtf(s);
        }
        __syncthreads();
        if (w < 8) out[mi] *= bsh[lane];
    }
}

extern "C" void kernel_launch(void* const* d_in, const int* in_sizes, int n_in,
                              void* d_out, int out_size) {
    const float* X     = (const float*)d_in[0];
    const float* cw    = (const float*)d_in[1];
    const float* scale = (const float*)d_in[2];
    float* out = (float*)d_out;

    static int configured = 0;
    if (!configured) {
        cudaFuncSetAttribute(fused_kernel, cudaFuncAttributeMaxDynamicSharedMemorySize,
                             SMEM_TOTAL);
        configured = 1;
    }

    reset_kernel<<<1, 32>>>();
    fused_kernel<<<GRID, NTHR, SMEM_TOTAL>>>(X, cw, scale, out);
}

// round 6
// speedup vs baseline: 1.2892x; 1.1891x over previous
#include <cuda_runtime.h>
#include <cstdint>

#define BB 2
#define DD 512
#define KK 32
#define NN 4096
#define NB 64
#define GRID 128
#define NTHR 1024
#define NCHOUT 32
#define ZSIZE (BB*DD*KK)

typedef unsigned long long ull;

// ---------- device scratch ----------
__device__ float g_Af[DD*KK];            // s^2
__device__ float g_Bf[DD*KK];            // -2 s^2 c
__device__ float g_C[KK];                // sum_d s^2 c^2
__device__ float g_S1part[GRID*KK];      // per-tile Q column sums
__device__ float g_Mpart[NCHOUT][BB*DD*KK];
__device__ float g_SS[BB*64*KK];
__device__ volatile unsigned g_bar;

// ---------- f32x2 helpers ----------
__device__ __forceinline__ ull pk2(float lo, float hi) {
    ull r; asm("mov.b64 %0, {%1,%2};" : "=l"(r) : "f"(lo), "f"(hi)); return r;
}
__device__ __forceinline__ void upk2(ull v, float& lo, float& hi) {
    asm("mov.b64 {%0,%1}, %2;" : "=f"(lo), "=f"(hi) : "l"(v));
}
__device__ __forceinline__ ull fma2(ull a, ull b, ull c) {
    ull d; asm("fma.rn.f32x2 %0, %1, %2, %3;" : "=l"(d) : "l"(a), "l"(b), "l"(c)); return d;
}

// ---------- grid barrier ----------
__device__ __forceinline__ void grid_sync(unsigned target) {
    __syncthreads();
    if (threadIdx.x == 0) {
        __threadfence();
        atomicAdd((unsigned*)&g_bar, 1u);
        while (g_bar < target) { __nanosleep(32); }
        __threadfence();
    }
    __syncthreads();
}

__global__ void reset_kernel() { if (threadIdx.x == 0) g_bar = 0; }

// ---------- smem layout ----------
#define OFF_XS0 0          // [64][64] 16KB
#define OFF_XS1 16384      // [64][64] 16KB
#define OFF_ASF 32768      // float[512][32] 64KB
#define OFF_BSF 98304      // float[512][32] 64KB
#define OFF_EP  32768      // alias: [32][16][32] 64KB
#define OFF_EF  98304      // alias: [64][32] 8KB
#define OFF_RED 106496     // [32][33]
#define SMEM_TOTAL 163840
// P2 aliases: Xs2[4][64][64] @0 (64KB), Qs2[4][64][32] @65536 (32KB)

__global__ __launch_bounds__(NTHR) void fused_kernel(const float* __restrict__ X,
                                                     const float* __restrict__ cw,
                                                     const float* __restrict__ scale,
                                                     float* __restrict__ out) {
    extern __shared__ unsigned char sm[];
    const int tid  = threadIdx.x;
    const int lane = tid & 31;
    const int w    = tid >> 5;           // 0..31
    const int bid  = blockIdx.x;

    // ============ P0: coefficients ============
    if (tid < 128) {
        int idx = bid*128 + tid;         // d*32+k
        float s = scale[idx];
        int d = idx >> 5, k = idx & 31;
        float c = cw[k*DD + d];
        g_Af[idx] = s*s;
        g_Bf[idx] = -2.f*s*s*c;
    }
    if (bid < KK) {
        float* red = (float*)sm;
        const int k = bid;
        float v = 0.f;
        if (tid < DD) {
            float s = scale[tid*KK + k];
            float c = cw[k*DD + tid];
            v = s*s*c*c;
        }
        red[tid] = v; __syncthreads();
        #pragma unroll
        for (int off = 512; off > 0; off >>= 1) {
            if (tid < off) red[tid] += red[tid + off];
            __syncthreads();
        }
        if (tid == 0) g_C[k] = red[0];
    }
    grid_sync(1*GRID);

    // ============ P1: E-GEMM + softmax -> Q ============
    {
        float* Asf = (float*)(sm + OFF_ASF);
        float* Bsf = (float*)(sm + OFF_BSF);
        // stage ALL coefficients once (4 float4 each per array)
        #pragma unroll
        for (int it = 0; it < 4; it++) {
            ((float4*)Asf)[tid + it*1024] = ((const float4*)g_Af)[tid + it*1024];
            ((float4*)Bsf)[tid + it*1024] = ((const float4*)g_Bf)[tid + it*1024];
        }

        const int ng = w >> 3;           // n-group 0..3 (16 n each)
        const int wd = w & 7;            // d slot
        const int n0 = bid * NB;
        const int b  = n0 >> 12;
        const float* Xb = X + (size_t)b*DD*NN + (n0 & (NN - 1));
        const int r = tid >> 4, c4 = tid & 15;

        // preload chunk 0
        float4 xpre = *(const float4*)(Xb + (size_t)r*NN + c4*4);
        *(float4*)((float*)(sm + OFF_XS0) + r*64 + c4*4) = xpre;
        __syncthreads();

        ull acc[8];
        #pragma unroll
        for (int i = 0; i < 8; i++) acc[i] = 0ull;

        #pragma unroll 1
        for (int c = 0; c < 8; c++) {
            const float* Xs = (const float*)(sm + ((c & 1) ? OFF_XS1 : OFF_XS0));
            if (c < 7)
                xpre = *(const float4*)(Xb + (size_t)((c+1)*64 + r)*NN + c4*4);
            const float* Ac = Asf + c*64*KK;
            const float* Bc = Bsf + c*64*KK;
            #pragma unroll
            for (int it = 0; it < 8; it++) {
                int dd = wd + it*8;
                float av = Ac[dd*KK + lane];
                float bv = Bc[dd*KK + lane];
                ull a2 = pk2(av, av), b2 = pk2(bv, bv);
                const float* xr = &Xs[dd*64 + ng*16];
                #pragma unroll
                for (int g = 0; g < 4; g++) {
                    longlong2 xv = *reinterpret_cast<const longlong2*>(xr + g*4);
                    ull x01 = (ull)xv.x, x23 = (ull)xv.y;
                    ull t0 = fma2(a2, x01, b2);
                    acc[2*g]   = fma2(x01, t0, acc[2*g]);
                    ull t1 = fma2(a2, x23, b2);
                    acc[2*g+1] = fma2(x23, t1, acc[2*g+1]);
                }
            }
            if (c < 7)
                *(float4*)((float*)(sm + ((c & 1) ? OFF_XS0 : OFF_XS1)) + r*64 + c4*4) = xpre;
            __syncthreads();
        }

        // dump partials Ep[w][16n][32k] (aliases Asf — done with it)
        float* Ep  = (float*)(sm + OFF_EP);
        float* Ef  = (float*)(sm + OFF_EF);
        float* red = (float*)(sm + OFF_RED);
        #pragma unroll
        for (int i = 0; i < 8; i++) {
            float lo, hi; upk2(acc[i], lo, hi);
            Ep[w*512 + (2*i  )*KK + lane] = lo;
            Ep[w*512 + (2*i+1)*KK + lane] = hi;
        }
        __syncthreads();
        // reduce 8 d-slot warps per n-group
        #pragma unroll
        for (int it = 0; it < 2; it++) {
            int idx = tid + it*1024;     // n*32+k
            int n = idx >> 5, k = idx & 31;
            int ngg = n >> 4, nl = n & 15;
            float s = 0.f;
            #pragma unroll
            for (int wdd = 0; wdd < 8; wdd++)
                s += Ep[(ngg*8 + wdd)*512 + nl*KK + k];
            Ef[idx] = s;
        }
        __syncthreads();

        // softmax: warp w handles 2 n
        float* Qout = out + ZSIZE;
        const float Ck = g_C[lane];
        float s1loc = 0.f;
        #pragma unroll
        for (int i = 0; i < 2; i++) {
            int n = w*2 + i;
            float arg = -0.5f * (Ef[n*KK + lane] + Ck);
            float m = arg;
            #pragma unroll
            for (int off = 16; off; off >>= 1) m = fmaxf(m, __shfl_xor_sync(~0u, m, off));
            float ex = __expf(arg - m);
            float ssum = ex;
            #pragma unroll
            for (int off = 16; off; off >>= 1) ssum += __shfl_xor_sync(~0u, ssum, off);
            float q = ex / ssum;
            Qout[(size_t)(n0 + n)*KK + lane] = q;
            s1loc += q;
        }
        red[w*33 + lane] = s1loc;
        __syncthreads();
        if (w == 0) {
            float s = 0.f;
            #pragma unroll
            for (int i = 0; i < 32; i++) s += red[i*33 + lane];
            g_S1part[bid*KK + lane] = s;
        }
    }
    grid_sync(2*GRID);

    // ============ P2: Mpart[nc*4+grp][b,d,k] = sum_n Q*x ============
    {
        float* Xs2 = (float*)sm;             // [4][64][64]
        float* Qs2 = (float*)(sm + 65536);   // [4][64][32]
        const int b   = bid >> 6;
        const int dt  = (bid >> 3) & 7;
        const int nc  = bid & 7;
        const int grp = w >> 3;              // subtile group 0..3
        const int wg  = w & 7;               // d rows wg*8..wg*8+7
        const int d0  = dt*64;

        const float* Qb = out + ZSIZE + (size_t)b*NN*KK;
        const float* Xb = X + (size_t)b*DD*NN;

        ull acc2[8];
        #pragma unroll
        for (int j = 0; j < 8; j++) acc2[j] = 0ull;

        #pragma unroll 1
        for (int pass = 0; pass < 2; pass++) {
            // stage 4 X tiles (64KB) + 4 Q tiles (32KB)
            #pragma unroll
            for (int it = 0; it < 4; it++) {
                int idx = tid + it*1024;
                int sl = idx >> 10, rr = (idx >> 4) & 63, cc = idx & 15;
                *(float4*)&Xs2[sl*4096 + rr*64 + cc*4] =
                    *(const float4*)(Xb + (size_t)(d0 + rr)*NN + nc*512 + (pass*4 + sl)*64 + cc*4);
            }
            #pragma unroll
            for (int it = 0; it < 2; it++) {
                int idx = tid + it*1024;
                int sl = idx >> 9, rem = idx & 511;
                *(float4*)&Qs2[sl*2048 + rem*4] =
                    *(const float4*)(Qb + ((size_t)(nc*512 + (pass*4 + sl)*64))*KK + rem*4);
            }
            __syncthreads();
            const float* Xt = &Xs2[grp*4096];
            const float* Qt = &Qs2[grp*2048];
            #pragma unroll
            for (int g = 0; g < 16; g++) {
                float q0 = Qt[(4*g+0)*KK + lane];
                float q1 = Qt[(4*g+1)*KK + lane];
                float q2 = Qt[(4*g+2)*KK + lane];
                float q3 = Qt[(4*g+3)*KK + lane];
                ull q01 = pk2(q0, q1), q23 = pk2(q2, q3);
                #pragma unroll
                for (int j = 0; j < 8; j++) {
                    longlong2 xv = *reinterpret_cast<const longlong2*>(&Xt[(wg*8+j)*64 + 4*g]);
                    acc2[j] = fma2(q01, (ull)xv.x, acc2[j]);
                    acc2[j] = fma2(q23, (ull)xv.y, acc2[j]);
                }
            }
            __syncthreads();
        }
        #pragma unroll
        for (int j = 0; j < 8; j++) {
            float lo, hi; upk2(acc2[j], lo, hi);
            g_Mpart[nc*4 + grp][((size_t)b*DD + d0 + wg*8 + j)*KK + lane] = lo + hi;
        }
    }
    grid_sync(3*GRID);

    // ============ P3: unnormalized Z + sumsq partials ============
    const int bf  = bid >> 6;
    const int dtf = bid & 63;
    const int d0f = dtf*8;
    const int dfw = d0f + (w & 7);
    const size_t mi = ((size_t)bf*DD + dfw)*KK + lane;
    {
        float* red = (float*)sm;            // [32][33]
        float* cwf = (float*)(sm + 4224);   // [32][9]
        float* bsh = (float*)(sm + 5376);   // [32]

        if (tid < 256) {
            int k = tid >> 3, dl = tid & 7;
            cwf[k*9 + dl] = cw[k*DD + d0f + dl];
        }
        float s1p = g_S1part[(bf*64 + w)*KK + lane]
                  + g_S1part[(bf*64 + 32 + w)*KK + lane];
        red[w*33 + lane] = s1p;
        __syncthreads();
        if (w == 0) {
            float s = 0.f;
            #pragma unroll
            for (int i = 0; i < 32; i++) s += red[i*33 + lane];
            bsh[lane] = 1.f / s;
        }
        __syncthreads();
        float z = 0.f;
        if (w < 8) {
            float m = 0.f;
            #pragma unroll
            for (int c = 0; c < NCHOUT; c++) m += g_Mpart[c][mi];
            z = scale[dfw*KK + lane] * (m*bsh[lane] - cwf[lane*9 + (w & 7)]);
            out[mi] = z;
        }
        __syncthreads();
        if (w < 8) red[w*33 + lane] = z*z;
        __syncthreads();
        if (w == 0) {
            float s = 0.f;
            #pragma unroll
            for (int i = 0; i < 8; i++) s += red[i*33 + lane];
            g_SS[(bf*64 + dtf)*KK + lane] = s;
        }
    }
    grid_sync(4*GRID);

    // ============ P4: rescale ============
    {
        float* red = (float*)sm;
        float* bsh = (float*)(sm + 5376);
        float ssp = g_SS[(bf*64 + w)*KK + lane]
                  + g_SS[(bf*64 + 32 + w)*KK + lane];
        red[w*33 + lane] = ssp;
        __syncthreads();
        if (w == 0) {
            float s = 0.f;
            #pragma unroll
            for (int i = 0; i < 32; i++) s += red[i*33 + lane];
            bsh[lane] = rsqrtf(s);
        }
        __syncthreads();
        if (w < 8) out[mi] *= bsh[lane];
    }
}

extern "C" void kernel_launch(void* const* d_in, const int* in_sizes, int n_in,
                              void* d_out, int out_size) {
    const float* X     = (const float*)d_in[0];
    const float* cw    = (const float*)d_in[1];
    const float* scale = (const float*)d_in[2];
    float* out = (float*)d_out;

    cudaFuncSetAttribute(fused_kernel, cudaFuncAttributeMaxDynamicSharedMemorySize,
                         SMEM_TOTAL);

    reset_kernel<<<1, 32>>>();
    fused_kernel<<<GRID, NTHR, SMEM_TOTAL>>>(X, cw, scale, out);
}